// round 1
// baseline (speedup 1.0000x reference)
#include <cuda_runtime.h>
#include <cuda_bf16.h>
#include <math.h>

#define BB   8
#define HW   5476
#define RTOT 43808          // BB*HW
#define NL   32
#define DIM  1024
#define LIN  768
#define NH   8
#define DK   128

// ---------------- scratch (device globals; no allocations allowed) ----------
__device__ float  g_vis [(size_t)RTOT * 1024];
__device__ float  g_q   [(size_t)RTOT * 1024];   // q_raw, later reused as mm
__device__ float  g_o   [(size_t)RTOT * 1024];   // attention out
__device__ float  g_lang[(size_t)RTOT * 1024];   // lang_raw
__device__ float  g_k   [BB * NH * DK * NL];     // [b][h][d][n]
__device__ float  g_v   [BB * NH * NL * DK];     // [b][h][n][d]
__device__ float2 g_sq  [BB * 1024];             // q-norm (mean, rstd)
__device__ float2 g_sl  [BB * 1024];             // lang-norm (mean, rstd)

// ---------------- k/v projection (masked), head-friendly layouts ------------
__global__ void __launch_bounds__(128)
kv_k(const float* __restrict__ l, const float* __restrict__ lm,
     const float* __restrict__ fkw, const float* __restrict__ fkb,
     const float* __restrict__ fvw, const float* __restrict__ fvb,
     float* __restrict__ kg, float* __restrict__ vg)
{
    extern __shared__ float l_sm[];       // NL*LIN = 24576 floats (96 KB)
    __shared__ float mask_sm[NL];
    const int h = blockIdx.x, b = blockIdx.y;
    const int tid = threadIdx.x;          // d in [0,128)

    for (int idx = tid; idx < NL * LIN; idx += 128)
        l_sm[idx] = l[(size_t)b * NL * LIN + idx];
    if (tid < NL) mask_sm[tid] = lm[b * NL + tid];
    __syncthreads();

    const int c = h * DK + tid;
    const float* wk = fkw + (size_t)c * LIN;
    const float* wv = fvw + (size_t)c * LIN;

    float ak[NL], av[NL];
#pragma unroll
    for (int n = 0; n < NL; n++) { ak[n] = 0.f; av[n] = 0.f; }

    for (int i = 0; i < LIN; i++) {
        const float a = wk[i];
        const float v = wv[i];
#pragma unroll
        for (int n = 0; n < NL; n++) {
            const float lv = l_sm[n * LIN + i];   // smem broadcast
            ak[n] = fmaf(a, lv, ak[n]);
            av[n] = fmaf(v, lv, av[n]);
        }
    }

    const float kb = fkb[c], vb = fvb[c];
    const size_t base = (size_t)(b * NH + h) * (DK * NL);
#pragma unroll
    for (int n = 0; n < NL; n++) {
        const float mk = mask_sm[n];
        kg[base + tid * NL + n] = (ak[n] + kb) * mk;   // [d][n]
        vg[base + n * DK + tid] = (av[n] + vb) * mk;   // [n][d]
    }
}

// ---------------- 128x128x8 fp32 GEMM: C = A @ W^T + bias (opt. GELU) -------
// A: [M,1024] row-major, W: [1024,1024] row-major, C: [M,1024]
__global__ void __launch_bounds__(256, 2)
sgemm_k(const float* __restrict__ A, const float* __restrict__ W,
        const float* __restrict__ bias, float* __restrict__ C,
        int M, int act_gelu)
{
    __shared__ float As[8][128];
    __shared__ float Bs[8][128];
    const int tid = threadIdx.x;
    const int bn = blockIdx.x * 128;
    const int bm = blockIdx.y * 128;
    const int tx = tid & 15;
    const int ty = tid >> 4;
    const int lrow = tid >> 1;
    const int lk   = (tid & 1) * 4;

    const float* Ap = A + (size_t)(bm + lrow) * 1024 + lk;
    const float* Wp = W + (size_t)(bn + lrow) * 1024 + lk;
    const bool aok = (bm + lrow) < M;

    float acc[8][8];
#pragma unroll
    for (int i = 0; i < 8; i++)
#pragma unroll
        for (int j = 0; j < 8; j++) acc[i][j] = 0.f;

    for (int k0 = 0; k0 < 1024; k0 += 8) {
        const float4 a4 = aok ? *(const float4*)Ap : make_float4(0.f, 0.f, 0.f, 0.f);
        const float4 w4 = *(const float4*)Wp;
        As[lk + 0][lrow] = a4.x; As[lk + 1][lrow] = a4.y;
        As[lk + 2][lrow] = a4.z; As[lk + 3][lrow] = a4.w;
        Bs[lk + 0][lrow] = w4.x; Bs[lk + 1][lrow] = w4.y;
        Bs[lk + 2][lrow] = w4.z; Bs[lk + 3][lrow] = w4.w;
        __syncthreads();
#pragma unroll
        for (int kk = 0; kk < 8; kk++) {
            float ra[8], rb[8];
            *(float4*)&ra[0] = *(const float4*)&As[kk][ty * 8];
            *(float4*)&ra[4] = *(const float4*)&As[kk][ty * 8 + 4];
            *(float4*)&rb[0] = *(const float4*)&Bs[kk][tx * 8];
            *(float4*)&rb[4] = *(const float4*)&Bs[kk][tx * 8 + 4];
#pragma unroll
            for (int i = 0; i < 8; i++)
#pragma unroll
                for (int j = 0; j < 8; j++)
                    acc[i][j] = fmaf(ra[i], rb[j], acc[i][j]);
        }
        __syncthreads();
        Ap += 8; Wp += 8;
    }

    float bv[8];
#pragma unroll
    for (int j = 0; j < 8; j++) bv[j] = bias[bn + tx * 8 + j];

#pragma unroll
    for (int i = 0; i < 8; i++) {
        const int row = bm + ty * 8 + i;
        if (row >= M) continue;
        float r[8];
#pragma unroll
        for (int j = 0; j < 8; j++) {
            float t = acc[i][j] + bv[j];
            if (act_gelu) t = 0.5f * t * (1.0f + erff(t * 0.70710678118654752f));
            r[j] = t;
        }
        float* Crow = C + (size_t)row * 1024 + bn + tx * 8;
        *(float4*)&Crow[0] = make_float4(r[0], r[1], r[2], r[3]);
        *(float4*)&Crow[4] = make_float4(r[4], r[5], r[6], r[7]);
    }
}

// ---------------- instance-norm stats: per (b, channel) over HW rows --------
__global__ void __launch_bounds__(256)
stats_k(const float* __restrict__ C, float2* __restrict__ st)
{
    __shared__ float s1[4][64];
    __shared__ float s2[4][64];
    const int b  = blockIdx.y;
    const int cg = blockIdx.x * 64;
    const int tc = threadIdx.x & 63;
    const int tr = threadIdx.x >> 6;
    const float* base = C + (size_t)b * HW * 1024 + cg + tc;
    float a = 0.f, a2 = 0.f;
    for (int r = tr; r < HW; r += 4) {
        const float v = base[(size_t)r * 1024];
        a += v; a2 += v * v;
    }
    s1[tr][tc] = a; s2[tr][tc] = a2;
    __syncthreads();
    if (tr == 0) {
        a  = s1[0][tc] + s1[1][tc] + s1[2][tc] + s1[3][tc];
        a2 = s2[0][tc] + s2[1][tc] + s2[2][tc] + s2[3][tc];
        const float inv = 1.0f / (float)HW;
        const float mean = a * inv;
        const float var  = a2 * inv - mean * mean;
        st[b * 1024 + cg + tc] = make_float2(mean, rsqrtf(var + 1e-5f));
    }
}

// ---------------- attention: (b, head, 64-row tile) -------------------------
__global__ void __launch_bounds__(128)
attn_k(const float* __restrict__ q, const float* __restrict__ kg,
       const float* __restrict__ vg, const float2* __restrict__ sq,
       const float* __restrict__ lm, float* __restrict__ o)
{
    extern __shared__ float sm[];
    float* q_sm = sm;                 // 64*128
    float* k_sm = sm + 8192;          // 128*32 [d][n]
    float* v_sm = sm + 12288;         // 32*128 [n][d]
    float* p_sm = sm + 16384;         // 64*32
    float* b_sm = sm + 18432;         // 32

    const int b = blockIdx.z, h = blockIdx.y;
    const int r0 = blockIdx.x * 64;
    const int tid = threadIdx.x;
    const int lane = tid & 31, wi = tid >> 5;

    const size_t headoff = (size_t)(b * NH + h) * (DK * NL);
    for (int idx = tid; idx < DK * NL; idx += 128) {
        k_sm[idx] = kg[headoff + idx];
        v_sm[idx] = vg[headoff + idx];
    }
    if (tid < NL) b_sm[tid] = 10000.0f * (lm[b * NL + tid] - 1.0f);

    const float2 st = sq[b * 1024 + h * DK + tid];
    const size_t qbase = (size_t)b * HW * 1024 + h * DK + tid;
#pragma unroll 4
    for (int r = 0; r < 64; r++) {
        const int row = r0 + r;
        const float val = (row < HW) ? q[qbase + (size_t)row * 1024] : 0.f;
        q_sm[r * 128 + tid] = (val - st.x) * st.y;
    }
    __syncthreads();

    // scores + softmax: warp wi handles rows wi*16 .. wi*16+15, lane = key n
    for (int rp = 0; rp < 16; rp += 2) {
        const int ra = wi * 16 + rp;
        const float* qa = q_sm + ra * 128;
        const float* qb = qa + 128;
        float s0 = 0.f, s1 = 0.f;
#pragma unroll 8
        for (int d = 0; d < 128; d++) {
            const float kk = k_sm[d * 32 + lane];
            s0 = fmaf(qa[d], kk, s0);
            s1 = fmaf(qb[d], kk, s1);
        }
        s0 = s0 * 0.03125f + b_sm[lane];   // KC^-0.5 = 1/32, masked bias
        s1 = s1 * 0.03125f + b_sm[lane];
        float m0 = s0, m1 = s1;
#pragma unroll
        for (int off = 16; off; off >>= 1) {
            m0 = fmaxf(m0, __shfl_xor_sync(0xffffffffu, m0, off));
            m1 = fmaxf(m1, __shfl_xor_sync(0xffffffffu, m1, off));
        }
        const float e0 = __expf(s0 - m0);
        const float e1 = __expf(s1 - m1);
        float t0 = e0, t1 = e1;
#pragma unroll
        for (int off = 16; off; off >>= 1) {
            t0 += __shfl_xor_sync(0xffffffffu, t0, off);
            t1 += __shfl_xor_sync(0xffffffffu, t1, off);
        }
        p_sm[ra * 32 + lane]       = e0 / t0;
        p_sm[(ra + 1) * 32 + lane] = e1 / t1;
    }
    __syncthreads();

    // O = P @ V^T, thread = output dim d, 4-row blocking
    const size_t obase = (size_t)b * HW * 1024 + h * DK + tid;
    for (int r = 0; r < 64; r += 4) {
        float o0 = 0.f, o1 = 0.f, o2 = 0.f, o3 = 0.f;
#pragma unroll
        for (int n = 0; n < NL; n++) {
            const float vv = v_sm[n * 128 + tid];
            o0 = fmaf(p_sm[(r + 0) * 32 + n], vv, o0);
            o1 = fmaf(p_sm[(r + 1) * 32 + n], vv, o1);
            o2 = fmaf(p_sm[(r + 2) * 32 + n], vv, o2);
            o3 = fmaf(p_sm[(r + 3) * 32 + n], vv, o3);
        }
        if (r0 + r + 0 < HW) o[obase + (size_t)(r0 + r + 0) * 1024] = o0;
        if (r0 + r + 1 < HW) o[obase + (size_t)(r0 + r + 1) * 1024] = o1;
        if (r0 + r + 2 < HW) o[obase + (size_t)(r0 + r + 2) * 1024] = o2;
        if (r0 + r + 3 < HW) o[obase + (size_t)(r0 + r + 3) * 1024] = o3;
    }
}

// ---------------- gated fusion: mm = vis * inorm(lang) ----------------------
__global__ void __launch_bounds__(256)
mm_k(const float* __restrict__ vis, const float* __restrict__ lang,
     const float2* __restrict__ sl, float* __restrict__ mm)
{
    const int i4 = blockIdx.x * blockDim.x + threadIdx.x;
    const int total4 = (RTOT * 1024) / 4;
    if (i4 >= total4) return;
    const size_t idx = (size_t)i4 * 4;
    const int r = (int)(idx >> 10);
    const int b = r / HW;
    const int c = (int)(idx & 1023);
    const float2 s0 = sl[b * 1024 + c + 0];
    const float2 s1 = sl[b * 1024 + c + 1];
    const float2 s2 = sl[b * 1024 + c + 2];
    const float2 s3 = sl[b * 1024 + c + 3];
    const float4 vv = *(const float4*)(vis + idx);
    const float4 lv = *(const float4*)(lang + idx);
    float4 ov;
    ov.x = vv.x * ((lv.x - s0.x) * s0.y);
    ov.y = vv.y * ((lv.y - s1.x) * s1.y);
    ov.z = vv.z * ((lv.z - s2.x) * s2.y);
    ov.w = vv.w * ((lv.w - s3.x) * s3.y);
    *(float4*)(mm + idx) = ov;
}

// ---------------- launcher ---------------------------------------------------
extern "C" void kernel_launch(void* const* d_in, const int* in_sizes, int n_in,
                              void* d_out, int out_size)
{
    const float* x      = (const float*)d_in[0];
    const float* l      = (const float*)d_in[1];
    const float* l_mask = (const float*)d_in[2];
    const float* vis_w  = (const float*)d_in[3];
    const float* vis_b  = (const float*)d_in[4];
    const float* fq_w   = (const float*)d_in[5];
    const float* fq_b   = (const float*)d_in[6];
    const float* fk_w   = (const float*)d_in[7];
    const float* fk_b   = (const float*)d_in[8];
    const float* fv_w   = (const float*)d_in[9];
    const float* fv_b   = (const float*)d_in[10];
    const float* W_w    = (const float*)d_in[11];
    const float* W_b    = (const float*)d_in[12];
    const float* pm_w   = (const float*)d_in[13];
    const float* pm_b   = (const float*)d_in[14];
    float* out = (float*)d_out;

    float *pvis, *pq, *po, *plang, *pk, *pv;
    float2 *psq, *psl;
    cudaGetSymbolAddress((void**)&pvis,  g_vis);
    cudaGetSymbolAddress((void**)&pq,    g_q);
    cudaGetSymbolAddress((void**)&po,    g_o);
    cudaGetSymbolAddress((void**)&plang, g_lang);
    cudaGetSymbolAddress((void**)&pk,    g_k);
    cudaGetSymbolAddress((void**)&pv,    g_v);
    cudaGetSymbolAddress((void**)&psq,   g_sq);
    cudaGetSymbolAddress((void**)&psl,   g_sl);

    cudaFuncSetAttribute(kv_k,   cudaFuncAttributeMaxDynamicSharedMemorySize, NL * LIN * 4);
    cudaFuncSetAttribute(attn_k, cudaFuncAttributeMaxDynamicSharedMemorySize, 18464 * 4);

    const dim3 gg(8, (RTOT + 127) / 128);

    // 1) k,v projection (masked)
    kv_k<<<dim3(NH, BB), 128, NL * LIN * 4>>>(l, l_mask, fk_w, fk_b, fv_w, fv_b, pk, pv);
    // 2) vis = GELU(x @ vis_w^T + b)
    sgemm_k<<<gg, 256>>>(x, vis_w, vis_b, pvis, RTOT, 1);
    // 3) q_raw = x @ fq_w^T + b
    sgemm_k<<<gg, 256>>>(x, fq_w, fq_b, pq, RTOT, 0);
    // 4) q instance-norm stats
    stats_k<<<dim3(16, BB), 256>>>(pq, psq);
    // 5) attention
    attn_k<<<dim3((HW + 63) / 64, NH, BB), 128, 18464 * 4>>>(pq, pk, pv, psq, l_mask, po);
    // 6) lang_raw = O @ W_w^T + b
    sgemm_k<<<gg, 256>>>(po, W_w, W_b, plang, RTOT, 0);
    // 7) lang instance-norm stats
    stats_k<<<dim3(16, BB), 256>>>(plang, psl);
    // 8) mm = vis * inorm(lang)   (reuse g_q as mm buffer)
    mm_k<<<(RTOT * 1024 / 4 + 255) / 256, 256>>>(pvis, plang, psl, pq);
    // 9) out = GELU(mm @ pm_w^T + b)
    sgemm_k<<<gg, 256>>>(pq, pm_w, pm_b, out, RTOT, 1);
}

// round 4
// speedup vs baseline: 1.9394x; 1.9394x over previous
#include <cuda_runtime.h>
#include <cuda_bf16.h>
#include <math.h>
#include <stdint.h>

#define BB   8
#define HW   5476
#define RTOT 43808          // BB*HW
#define NL   32
#define NH   8
#define DK   128
#define LIN  768

#define KCAT 3072           // [hi | X | Y] split-K concat
#define Bb 128              // block tile M
#define BN 128              // block tile N
#define BK 64               // k tile (bf16 elements) = 128B rows
#define NKT (KCAT / BK)     // 48
#define SROWH 72            // padded smem row stride in halves (128B + 16B pad)
#define STAGE_H (128 * SROWH)             // halves per operand per stage
#define GEMM_SMEM (4 * STAGE_H * 2)       // bytes: 2 stages x (A + B)

// ---------------- scratch (device globals; no allocations allowed) ----------
__device__ float  g_vis [(size_t)RTOT * 1024];
__device__ float  g_q   [(size_t)RTOT * 1024];   // q_raw, later reused as mm
__device__ float  g_o   [(size_t)RTOT * 1024];   // attention out
__device__ float  g_lang[(size_t)RTOT * 1024];   // lang_raw
__device__ __nv_bfloat16 g_acat[(size_t)RTOT * KCAT];      // split activations
__device__ __nv_bfloat16 g_wcat[4][(size_t)1024 * KCAT];   // split weights
__device__ float  g_k   [BB * NH * DK * NL];     // [b][h][d][n]
__device__ float  g_v   [BB * NH * NL * DK];     // [b][h][n][d]
__device__ float2 g_sq  [BB * 1024];             // q-norm (mean, rstd)
__device__ float2 g_sl  [BB * 1024];             // lang-norm (mean, rstd)

// ---------------- helpers ----------------------------------------------------
__device__ __forceinline__ void cp_async16(uint32_t dst, const void* src, int szbytes) {
    asm volatile("cp.async.cg.shared.global [%0], [%1], 16, %2;"
                 :: "r"(dst), "l"(src), "r"(szbytes) : "memory");
}
__device__ __forceinline__ uint32_t smem_u32(const void* p) {
    uint32_t a;
    asm("{ .reg .u64 t; cvta.to.shared.u64 t, %1; cvt.u32.u64 %0, t; }" : "=r"(a) : "l"(p));
    return a;
}
__device__ __forceinline__ void mma_bf16(float& c0, float& c1, float& c2, float& c3,
                                         uint32_t a0, uint32_t a1, uint32_t a2, uint32_t a3,
                                         uint32_t b0, uint32_t b1) {
    asm volatile("mma.sync.aligned.m16n8k16.row.col.f32.bf16.bf16.f32 "
                 "{%0,%1,%2,%3}, {%4,%5,%6,%7}, {%8,%9}, {%0,%1,%2,%3};"
                 : "+f"(c0), "+f"(c1), "+f"(c2), "+f"(c3)
                 : "r"(a0), "r"(a1), "r"(a2), "r"(a3), "r"(b0), "r"(b1));
}

// ---------------- split conversion: fp32 -> bf16 [hi | X | Y] ----------------
// writes hi at col c, hi duplicate at hi2_off+c, lo at lo_off+c
__global__ void __launch_bounds__(256)
conv_k(const float* __restrict__ A, __nv_bfloat16* __restrict__ out,
       int nrows, int lo_off, int hi2_off)
{
    const size_t i = (size_t)blockIdx.x * 256 + threadIdx.x;  // one per 4 elems
    const size_t tot = (size_t)nrows * 256;
    if (i >= tot) return;
    const size_t row = i >> 8;
    const int c4 = (int)(i & 255) * 4;
    const float4 a = *(const float4*)(A + row * 1024 + c4);
    __nv_bfloat16 h0 = __float2bfloat16_rn(a.x);
    __nv_bfloat16 h1 = __float2bfloat16_rn(a.y);
    __nv_bfloat16 h2 = __float2bfloat16_rn(a.z);
    __nv_bfloat16 h3 = __float2bfloat16_rn(a.w);
    __nv_bfloat16 l0 = __float2bfloat16_rn(a.x - __bfloat162float(h0));
    __nv_bfloat16 l1 = __float2bfloat16_rn(a.y - __bfloat162float(h1));
    __nv_bfloat16 l2 = __float2bfloat16_rn(a.z - __bfloat162float(h2));
    __nv_bfloat16 l3 = __float2bfloat16_rn(a.w - __bfloat162float(h3));
    __nv_bfloat16* base = out + row * KCAT;
    ushort4 hv = make_ushort4(*(unsigned short*)&h0, *(unsigned short*)&h1,
                              *(unsigned short*)&h2, *(unsigned short*)&h3);
    ushort4 lv = make_ushort4(*(unsigned short*)&l0, *(unsigned short*)&l1,
                              *(unsigned short*)&l2, *(unsigned short*)&l3);
    *(ushort4*)(base + c4)           = hv;
    *(ushort4*)(base + hi2_off + c4) = hv;
    *(ushort4*)(base + lo_off + c4)  = lv;
}

// ---------------- bf16 tensor GEMM: C[M,1024] = A_cat @ W_cat^T + bias ------
// A: [M,KCAT] bf16 row-major, W: [1024,KCAT] bf16 row-major
__global__ void __launch_bounds__(256, 2)
tgemm_k(const __nv_bfloat16* __restrict__ A, const __nv_bfloat16* __restrict__ W,
        const float* __restrict__ bias, float* __restrict__ C,
        int M, int act_gelu)
{
    extern __shared__ __nv_bfloat16 sm[];
    // layout: As[2][128][SROWH], Bs[2][128][SROWH]
    const __nv_bfloat16* As[2] = { sm,               sm + STAGE_H };
    const __nv_bfloat16* Bs[2] = { sm + 2 * STAGE_H, sm + 3 * STAGE_H };
    const uint32_t smb = smem_u32(sm);

    const int tid  = threadIdx.x;
    const int lane = tid & 31;
    const int wid  = tid >> 5;
    const int wm   = wid & 1;        // 2 warps in M (64 rows each)
    const int wn   = wid >> 1;       // 4 warps in N (32 cols each)
    const int tg   = lane >> 2;
    const int t4   = lane & 3;
    const int m0   = blockIdx.y * Bb;
    const int n0   = blockIdx.x * BN;

    float acc[4][4][4];
#pragma unroll
    for (int i = 0; i < 4; i++)
#pragma unroll
        for (int j = 0; j < 4; j++)
#pragma unroll
            for (int r = 0; r < 4; r++) acc[i][j][r] = 0.f;

    // 1024 16B-chunks per (A+B) stage: 128 rows x 8 chunks each operand
    auto load_stage = [&](int s, int k0) {
        const uint32_t abase = smb + (uint32_t)(s * STAGE_H) * 2u;
        const uint32_t bbase = smb + (uint32_t)((2 + s) * STAGE_H) * 2u;
#pragma unroll
        for (int t = 0; t < 4; t++) {
            const int chunk = tid + t * 256;       // 0..1023
            const int row = chunk >> 3;
            const int c8  = (chunk & 7) * 8;       // halves
            const uint32_t soff = (uint32_t)(row * SROWH + c8) * 2u;
            // A (guard M)
            const int grow = m0 + row;
            const int ok = (grow < M) ? 16 : 0;
            const __nv_bfloat16* asrc = A + (size_t)(ok ? grow : 0) * KCAT + k0 + c8;
            cp_async16(abase + soff, asrc, ok);
            // B (always valid)
            const __nv_bfloat16* bsrc = W + (size_t)(n0 + row) * KCAT + k0 + c8;
            cp_async16(bbase + soff, bsrc, 16);
        }
        asm volatile("cp.async.commit_group;" ::: "memory");
    };

    load_stage(0, 0);

    for (int kt = 0; kt < NKT; kt++) {
        if (kt + 1 < NKT) {
            load_stage((kt + 1) & 1, (kt + 1) * BK);
            asm volatile("cp.async.wait_group 1;" ::: "memory");
        } else {
            asm volatile("cp.async.wait_group 0;" ::: "memory");
        }
        __syncthreads();

        const __nv_bfloat16* Asm = As[kt & 1];
        const __nv_bfloat16* Bsm = Bs[kt & 1];
#pragma unroll
        for (int k16 = 0; k16 < 4; k16++) {
            const int kk = k16 * 16;
            uint32_t af[4][4], bf[4][2];
#pragma unroll
            for (int mt = 0; mt < 4; mt++) {
                const int r = wm * 64 + mt * 16 + tg;
                const __nv_bfloat16* p0 = Asm + r * SROWH + kk + 2 * t4;
                const __nv_bfloat16* p1 = p0 + 8 * SROWH;
                af[mt][0] = *(const uint32_t*)p0;
                af[mt][1] = *(const uint32_t*)p1;
                af[mt][2] = *(const uint32_t*)(p0 + 8);
                af[mt][3] = *(const uint32_t*)(p1 + 8);
            }
#pragma unroll
            for (int nt = 0; nt < 4; nt++) {
                const int n = wn * 32 + nt * 8 + tg;
                const __nv_bfloat16* p = Bsm + n * SROWH + kk + 2 * t4;
                bf[nt][0] = *(const uint32_t*)p;
                bf[nt][1] = *(const uint32_t*)(p + 8);
            }
#pragma unroll
            for (int mt = 0; mt < 4; mt++)
#pragma unroll
                for (int nt = 0; nt < 4; nt++)
                    mma_bf16(acc[mt][nt][0], acc[mt][nt][1], acc[mt][nt][2], acc[mt][nt][3],
                             af[mt][0], af[mt][1], af[mt][2], af[mt][3],
                             bf[nt][0], bf[nt][1]);
        }
        __syncthreads();
    }

    // epilogue: c0,c1 at (row tg, col 2t4, 2t4+1), c2,c3 at (row tg+8)
#pragma unroll
    for (int mt = 0; mt < 4; mt++) {
        const int ra = m0 + wm * 64 + mt * 16 + tg;
        const int rb = ra + 8;
#pragma unroll
        for (int nt = 0; nt < 4; nt++) {
            const int col = n0 + wn * 32 + nt * 8 + t4 * 2;
            const float bx = bias[col], by = bias[col + 1];
            float v0 = acc[mt][nt][0] + bx;
            float v1 = acc[mt][nt][1] + by;
            float v2 = acc[mt][nt][2] + bx;
            float v3 = acc[mt][nt][3] + by;
            if (act_gelu) {
                v0 = 0.5f * v0 * (1.0f + erff(v0 * 0.70710678118654752f));
                v1 = 0.5f * v1 * (1.0f + erff(v1 * 0.70710678118654752f));
                v2 = 0.5f * v2 * (1.0f + erff(v2 * 0.70710678118654752f));
                v3 = 0.5f * v3 * (1.0f + erff(v3 * 0.70710678118654752f));
            }
            if (ra < M) *(float2*)(C + (size_t)ra * 1024 + col) = make_float2(v0, v1);
            if (rb < M) *(float2*)(C + (size_t)rb * 1024 + col) = make_float2(v2, v3);
        }
    }
}

// ---------------- k/v projection (masked), head-friendly layouts ------------
__global__ void __launch_bounds__(128)
kv_k(const float* __restrict__ l, const float* __restrict__ lm,
     const float* __restrict__ fkw, const float* __restrict__ fkb,
     const float* __restrict__ fvw, const float* __restrict__ fvb,
     float* __restrict__ kg, float* __restrict__ vg)
{
    extern __shared__ float l_sm[];
    __shared__ float mask_sm[NL];
    const int h = blockIdx.x, b = blockIdx.y;
    const int tid = threadIdx.x;

    for (int idx = tid; idx < NL * LIN; idx += 128)
        l_sm[idx] = l[(size_t)b * NL * LIN + idx];
    if (tid < NL) mask_sm[tid] = lm[b * NL + tid];
    __syncthreads();

    const int c = h * DK + tid;
    const float* wk = fkw + (size_t)c * LIN;
    const float* wv = fvw + (size_t)c * LIN;

    float ak[NL], av[NL];
#pragma unroll
    for (int n = 0; n < NL; n++) { ak[n] = 0.f; av[n] = 0.f; }
    for (int i = 0; i < LIN; i++) {
        const float a = wk[i];
        const float v = wv[i];
#pragma unroll
        for (int n = 0; n < NL; n++) {
            const float lv = l_sm[n * LIN + i];
            ak[n] = fmaf(a, lv, ak[n]);
            av[n] = fmaf(v, lv, av[n]);
        }
    }
    const float kb = fkb[c], vb = fvb[c];
    const size_t base = (size_t)(b * NH + h) * (DK * NL);
#pragma unroll
    for (int n = 0; n < NL; n++) {
        const float mk = mask_sm[n];
        kg[base + tid * NL + n] = (ak[n] + kb) * mk;
        vg[base + n * DK + tid] = (av[n] + vb) * mk;
    }
}

// ---------------- instance-norm stats ---------------------------------------
__global__ void __launch_bounds__(256)
stats_k(const float* __restrict__ C, float2* __restrict__ st)
{
    __shared__ float s1[4][64];
    __shared__ float s2[4][64];
    const int b  = blockIdx.y;
    const int cg = blockIdx.x * 64;
    const int tc = threadIdx.x & 63;
    const int tr = threadIdx.x >> 6;
    const float* base = C + (size_t)b * HW * 1024 + cg + tc;
    float a = 0.f, a2 = 0.f;
    for (int r = tr; r < HW; r += 4) {
        const float v = base[(size_t)r * 1024];
        a += v; a2 += v * v;
    }
    s1[tr][tc] = a; s2[tr][tc] = a2;
    __syncthreads();
    if (tr == 0) {
        a  = s1[0][tc] + s1[1][tc] + s1[2][tc] + s1[3][tc];
        a2 = s2[0][tc] + s2[1][tc] + s2[2][tc] + s2[3][tc];
        const float inv = 1.0f / (float)HW;
        const float mean = a * inv;
        const float var  = a2 * inv - mean * mean;
        st[b * 1024 + cg + tc] = make_float2(mean, rsqrtf(var + 1e-5f));
    }
}

// ---------------- attention --------------------------------------------------
__global__ void __launch_bounds__(128)
attn_k(const float* __restrict__ q, const float* __restrict__ kg,
       const float* __restrict__ vg, const float2* __restrict__ sq,
       const float* __restrict__ lm, float* __restrict__ o)
{
    extern __shared__ float smn[];
    float* q_sm = smn;
    float* k_sm = smn + 8192;
    float* v_sm = smn + 12288;
    float* p_sm = smn + 16384;
    float* b_sm = smn + 18432;

    const int b = blockIdx.z, h = blockIdx.y;
    const int r0 = blockIdx.x * 64;
    const int tid = threadIdx.x;
    const int lane = tid & 31, wi = tid >> 5;

    const size_t headoff = (size_t)(b * NH + h) * (DK * NL);
    for (int idx = tid; idx < DK * NL; idx += 128) {
        k_sm[idx] = kg[headoff + idx];
        v_sm[idx] = vg[headoff + idx];
    }
    if (tid < NL) b_sm[tid] = 10000.0f * (lm[b * NL + tid] - 1.0f);

    const float2 st = sq[b * 1024 + h * DK + tid];
    const size_t qbase = (size_t)b * HW * 1024 + h * DK + tid;
#pragma unroll 4
    for (int r = 0; r < 64; r++) {
        const int row = r0 + r;
        const float val = (row < HW) ? q[qbase + (size_t)row * 1024] : 0.f;
        q_sm[r * 128 + tid] = (val - st.x) * st.y;
    }
    __syncthreads();

    for (int rp = 0; rp < 16; rp += 2) {
        const int ra = wi * 16 + rp;
        const float* qa = q_sm + ra * 128;
        const float* qb = qa + 128;
        float s0 = 0.f, s1 = 0.f;
#pragma unroll 8
        for (int d = 0; d < 128; d++) {
            const float kk = k_sm[d * 32 + lane];
            s0 = fmaf(qa[d], kk, s0);
            s1 = fmaf(qb[d], kk, s1);
        }
        s0 = s0 * 0.03125f + b_sm[lane];
        s1 = s1 * 0.03125f + b_sm[lane];
        float m0 = s0, m1 = s1;
#pragma unroll
        for (int off = 16; off; off >>= 1) {
            m0 = fmaxf(m0, __shfl_xor_sync(0xffffffffu, m0, off));
            m1 = fmaxf(m1, __shfl_xor_sync(0xffffffffu, m1, off));
        }
        const float e0 = __expf(s0 - m0);
        const float e1 = __expf(s1 - m1);
        float t0 = e0, t1 = e1;
#pragma unroll
        for (int off = 16; off; off >>= 1) {
            t0 += __shfl_xor_sync(0xffffffffu, t0, off);
            t1 += __shfl_xor_sync(0xffffffffu, t1, off);
        }
        p_sm[ra * 32 + lane]       = e0 / t0;
        p_sm[(ra + 1) * 32 + lane] = e1 / t1;
    }
    __syncthreads();

    const size_t obase = (size_t)b * HW * 1024 + h * DK + tid;
    for (int r = 0; r < 64; r += 4) {
        float o0 = 0.f, o1 = 0.f, o2 = 0.f, o3 = 0.f;
#pragma unroll
        for (int n = 0; n < NL; n++) {
            const float vv = v_sm[n * 128 + tid];
            o0 = fmaf(p_sm[(r + 0) * 32 + n], vv, o0);
            o1 = fmaf(p_sm[(r + 1) * 32 + n], vv, o1);
            o2 = fmaf(p_sm[(r + 2) * 32 + n], vv, o2);
            o3 = fmaf(p_sm[(r + 3) * 32 + n], vv, o3);
        }
        if (r0 + r + 0 < HW) o[obase + (size_t)(r0 + r + 0) * 1024] = o0;
        if (r0 + r + 1 < HW) o[obase + (size_t)(r0 + r + 1) * 1024] = o1;
        if (r0 + r + 2 < HW) o[obase + (size_t)(r0 + r + 2) * 1024] = o2;
        if (r0 + r + 3 < HW) o[obase + (size_t)(r0 + r + 3) * 1024] = o3;
    }
}

// ---------------- gated fusion ----------------------------------------------
__global__ void __launch_bounds__(256)
mm_k(const float* __restrict__ vis, const float* __restrict__ lang,
     const float2* __restrict__ sl, float* __restrict__ mm)
{
    const int i4 = blockIdx.x * blockDim.x + threadIdx.x;
    const int total4 = (RTOT * 1024) / 4;
    if (i4 >= total4) return;
    const size_t idx = (size_t)i4 * 4;
    const int r = (int)(idx >> 10);
    const int b = r / HW;
    const int c = (int)(idx & 1023);
    const float2 s0 = sl[b * 1024 + c + 0];
    const float2 s1 = sl[b * 1024 + c + 1];
    const float2 s2 = sl[b * 1024 + c + 2];
    const float2 s3 = sl[b * 1024 + c + 3];
    const float4 vv = *(const float4*)(vis + idx);
    const float4 lv = *(const float4*)(lang + idx);
    float4 ov;
    ov.x = vv.x * ((lv.x - s0.x) * s0.y);
    ov.y = vv.y * ((lv.y - s1.x) * s1.y);
    ov.z = vv.z * ((lv.z - s2.x) * s2.y);
    ov.w = vv.w * ((lv.w - s3.x) * s3.y);
    *(float4*)(mm + idx) = ov;
}

// ---------------- launcher ---------------------------------------------------
extern "C" void kernel_launch(void* const* d_in, const int* in_sizes, int n_in,
                              void* d_out, int out_size)
{
    const float* x      = (const float*)d_in[0];
    const float* l      = (const float*)d_in[1];
    const float* l_mask = (const float*)d_in[2];
    const float* vis_w  = (const float*)d_in[3];
    const float* vis_b  = (const float*)d_in[4];
    const float* fq_w   = (const float*)d_in[5];
    const float* fq_b   = (const float*)d_in[6];
    const float* fk_w   = (const float*)d_in[7];
    const float* fk_b   = (const float*)d_in[8];
    const float* fv_w   = (const float*)d_in[9];
    const float* fv_b   = (const float*)d_in[10];
    const float* W_w    = (const float*)d_in[11];
    const float* W_b    = (const float*)d_in[12];
    const float* pm_w   = (const float*)d_in[13];
    const float* pm_b   = (const float*)d_in[14];
    float* out = (float*)d_out;

    float *pvis, *pq, *po, *plang, *pk, *pv;
    __nv_bfloat16 *pacat, *pwcat;
    float2 *psq, *psl;
    cudaGetSymbolAddress((void**)&pvis,  g_vis);
    cudaGetSymbolAddress((void**)&pq,    g_q);
    cudaGetSymbolAddress((void**)&po,    g_o);
    cudaGetSymbolAddress((void**)&plang, g_lang);
    cudaGetSymbolAddress((void**)&pacat, g_acat);
    cudaGetSymbolAddress((void**)&pwcat, g_wcat);
    cudaGetSymbolAddress((void**)&pk,    g_k);
    cudaGetSymbolAddress((void**)&pv,    g_v);
    cudaGetSymbolAddress((void**)&psq,   g_sq);
    cudaGetSymbolAddress((void**)&psl,   g_sl);
    __nv_bfloat16* wc0 = pwcat;
    __nv_bfloat16* wc1 = pwcat + (size_t)1024 * KCAT;
    __nv_bfloat16* wc2 = pwcat + (size_t)2 * 1024 * KCAT;
    __nv_bfloat16* wc3 = pwcat + (size_t)3 * 1024 * KCAT;

    cudaFuncSetAttribute(kv_k,    cudaFuncAttributeMaxDynamicSharedMemorySize, NL * LIN * 4);
    cudaFuncSetAttribute(attn_k,  cudaFuncAttributeMaxDynamicSharedMemorySize, 18464 * 4);
    cudaFuncSetAttribute(tgemm_k, cudaFuncAttributeMaxDynamicSharedMemorySize, GEMM_SMEM);

    const dim3 gg(1024 / BN, (RTOT + Bb - 1) / Bb);

    // weight splits: [hi | hi | lo]  (hi2_off=1024, lo_off=2048)
    conv_k<<<1024, 256>>>(vis_w, wc0, 1024, 2048, 1024);
    conv_k<<<1024, 256>>>(fq_w,  wc1, 1024, 2048, 1024);
    conv_k<<<1024, 256>>>(W_w,   wc2, 1024, 2048, 1024);
    conv_k<<<1024, 256>>>(pm_w,  wc3, 1024, 2048, 1024);

    // k,v projection (masked)
    kv_k<<<dim3(NH, BB), 128, NL * LIN * 4>>>(l, l_mask, fk_w, fk_b, fv_w, fv_b, pk, pv);

    // x split: [hi | lo | hi]  (lo_off=1024, hi2_off=2048)
    conv_k<<<RTOT, 256>>>(x, pacat, RTOT, 1024, 2048);
    // vis = GELU(x @ vis_w^T + b)
    tgemm_k<<<gg, 256, GEMM_SMEM>>>(pacat, wc0, vis_b, pvis, RTOT, 1);
    // q_raw = x @ fq_w^T + b
    tgemm_k<<<gg, 256, GEMM_SMEM>>>(pacat, wc1, fq_b, pq, RTOT, 0);
    // q instance-norm stats
    stats_k<<<dim3(16, BB), 256>>>(pq, psq);
    // attention
    attn_k<<<dim3((HW + 63) / 64, NH, BB), 128, 18464 * 4>>>(pq, pk, pv, psq, l_mask, po);
    // o split
    conv_k<<<RTOT, 256>>>(po, pacat, RTOT, 1024, 2048);
    // lang_raw = O @ W_w^T + b
    tgemm_k<<<gg, 256, GEMM_SMEM>>>(pacat, wc2, W_b, plang, RTOT, 0);
    // lang instance-norm stats
    stats_k<<<dim3(16, BB), 256>>>(plang, psl);
    // mm = vis * inorm(lang)   (into g_q)
    mm_k<<<(RTOT * 1024 / 4 + 255) / 256, 256>>>(pvis, plang, psl, pq);
    // mm split
    conv_k<<<RTOT, 256>>>(pq, pacat, RTOT, 1024, 2048);
    // out = GELU(mm @ pm_w^T + b)
    tgemm_k<<<gg, 256, GEMM_SMEM>>>(pacat, wc3, pm_b, out, RTOT, 1);
}

// round 5
// speedup vs baseline: 2.2585x; 1.1645x over previous
#include <cuda_runtime.h>
#include <cuda_bf16.h>
#include <math.h>
#include <stdint.h>

#define BB   8
#define HW   5476
#define RTOT 43808          // BB*HW
#define NL   32
#define NH   8
#define DK   128
#define LIN  768

#define KCAT 3072           // A:[hi|lo|hi]  W:[hi|hi|lo]
#define BM 128              // CTA tile M
#define BN 256              // CTA tile N
#define BK 64               // k tile (bf16) = 128B rows
#define NKT (KCAT / BK)     // 48
#define SROWH 72            // smem row stride in halves (128B + 16B pad)
#define A_BYTES (BM * SROWH * 2)
#define B_BYTES (BN * SROWH * 2)
#define STAGE_BYTES (A_BYTES + B_BYTES)      // 55296
#define GEMM_SMEM (3 * STAGE_BYTES)          // 165888

// ---------------- scratch (device globals; no allocations allowed) ----------
__device__ float  g_vis [(size_t)RTOT * 1024];
__device__ float  g_q   [(size_t)RTOT * 1024];
__device__ float  g_lang[(size_t)RTOT * 1024];
__device__ __nv_bfloat16 g_acat[(size_t)RTOT * KCAT];      // split activations
__device__ __nv_bfloat16 g_wcat[4][(size_t)1024 * KCAT];   // split weights
__device__ float  g_k   [BB * NH * DK * NL];     // [b][h][d][n]
__device__ float  g_v   [BB * NH * NL * DK];     // [b][h][n][d]
__device__ float2 g_sq  [BB * 1024];
__device__ float2 g_sl  [BB * 1024];

// ---------------- helpers ----------------------------------------------------
__device__ __forceinline__ void cp_async16(uint32_t dst, const void* src, int szbytes) {
    asm volatile("cp.async.cg.shared.global [%0], [%1], 16, %2;"
                 :: "r"(dst), "l"(src), "r"(szbytes) : "memory");
}
__device__ __forceinline__ uint32_t smem_u32(const void* p) {
    uint32_t a;
    asm("{ .reg .u64 t; cvta.to.shared.u64 t, %1; cvt.u32.u64 %0, t; }" : "=r"(a) : "l"(p));
    return a;
}
__device__ __forceinline__ void ldm_x4(uint32_t& r0, uint32_t& r1, uint32_t& r2,
                                       uint32_t& r3, uint32_t addr) {
    asm volatile("ldmatrix.sync.aligned.m8n8.x4.shared.b16 {%0,%1,%2,%3}, [%4];"
                 : "=r"(r0), "=r"(r1), "=r"(r2), "=r"(r3) : "r"(addr));
}
__device__ __forceinline__ void mma_bf16(float& c0, float& c1, float& c2, float& c3,
                                         uint32_t a0, uint32_t a1, uint32_t a2, uint32_t a3,
                                         uint32_t b0, uint32_t b1) {
    asm volatile("mma.sync.aligned.m16n8k16.row.col.f32.bf16.bf16.f32 "
                 "{%0,%1,%2,%3}, {%4,%5,%6,%7}, {%8,%9}, {%0,%1,%2,%3};"
                 : "+f"(c0), "+f"(c1), "+f"(c2), "+f"(c3)
                 : "r"(a0), "r"(a1), "r"(a2), "r"(a3), "r"(b0), "r"(b1));
}
__device__ __forceinline__ float gelu_f(float t) {
    return 0.5f * t * (1.0f + erff(t * 0.70710678118654752f));
}

// ---------------- split conversion: fp32 -> bf16 [hi | X | Y] ----------------
__global__ void __launch_bounds__(256)
conv_k(const float* __restrict__ A, __nv_bfloat16* __restrict__ out,
       int nrows, int lo_off, int hi2_off)
{
    const size_t i = (size_t)blockIdx.x * 256 + threadIdx.x;
    const size_t tot = (size_t)nrows * 256;
    if (i >= tot) return;
    const size_t row = i >> 8;
    const int c4 = (int)(i & 255) * 4;
    const float4 a = *(const float4*)(A + row * 1024 + c4);
    __nv_bfloat16 h0 = __float2bfloat16_rn(a.x);
    __nv_bfloat16 h1 = __float2bfloat16_rn(a.y);
    __nv_bfloat16 h2 = __float2bfloat16_rn(a.z);
    __nv_bfloat16 h3 = __float2bfloat16_rn(a.w);
    __nv_bfloat16 l0 = __float2bfloat16_rn(a.x - __bfloat162float(h0));
    __nv_bfloat16 l1 = __float2bfloat16_rn(a.y - __bfloat162float(h1));
    __nv_bfloat16 l2 = __float2bfloat16_rn(a.z - __bfloat162float(h2));
    __nv_bfloat16 l3 = __float2bfloat16_rn(a.w - __bfloat162float(h3));
    __nv_bfloat16* base = out + row * KCAT;
    ushort4 hv = make_ushort4(*(unsigned short*)&h0, *(unsigned short*)&h1,
                              *(unsigned short*)&h2, *(unsigned short*)&h3);
    ushort4 lv = make_ushort4(*(unsigned short*)&l0, *(unsigned short*)&l1,
                              *(unsigned short*)&l2, *(unsigned short*)&l3);
    *(ushort4*)(base + c4)           = hv;
    *(ushort4*)(base + hi2_off + c4) = hv;
    *(ushort4*)(base + lo_off + c4)  = lv;
}

// ---------------- bf16 tensor GEMM, 128x256 CTA, 3-stage, ldmatrix ----------
// A: [M,KCAT] bf16, W: [Ntot,KCAT] bf16; dual output halves (fused layers)
__global__ void __launch_bounds__(512, 1)
tgemm_k(const __nv_bfloat16* __restrict__ A, const __nv_bfloat16* __restrict__ W,
        const float* __restrict__ bias0, const float* __restrict__ bias1,
        float* __restrict__ C0, float* __restrict__ C1,
        int M, int act0, int act1)
{
    extern __shared__ __nv_bfloat16 sm[];
    const uint32_t smb = smem_u32(sm);

    const int tid  = threadIdx.x;
    const int lane = tid & 31;
    const int wid  = tid >> 5;
    const int wm   = wid & 1;        // 2 warps in M (64 rows)
    const int wn   = wid >> 1;       // 8 warps in N (32 cols)
    const int tg   = lane >> 2;
    const int t4   = lane & 3;
    const int m0   = blockIdx.y * BM;
    const int n0   = blockIdx.x * BN;

    float acc[4][4][4];
#pragma unroll
    for (int i = 0; i < 4; i++)
#pragma unroll
        for (int j = 0; j < 4; j++)
#pragma unroll
            for (int r = 0; r < 4; r++) acc[i][j][r] = 0.f;

    auto load_stage = [&](int s, int k0) {
        const uint32_t ab = smb + (uint32_t)(s * STAGE_BYTES);
        const uint32_t bb = ab + A_BYTES;
#pragma unroll
        for (int t = 0; t < 2; t++) {               // A: 1024 chunks
            const int ch  = tid + t * 512;
            const int row = ch >> 3;
            const int c8  = (ch & 7) * 8;
            const int grow = m0 + row;
            const int ok = (grow < M) ? 16 : 0;
            const __nv_bfloat16* src = A + (size_t)(ok ? grow : 0) * KCAT + k0 + c8;
            cp_async16(ab + (uint32_t)(row * SROWH + c8) * 2u, src, ok);
        }
#pragma unroll
        for (int t = 0; t < 4; t++) {               // B: 2048 chunks
            const int ch  = tid + t * 512;
            const int row = ch >> 3;
            const int c8  = (ch & 7) * 8;
            const __nv_bfloat16* src = W + (size_t)(n0 + row) * KCAT + k0 + c8;
            cp_async16(bb + (uint32_t)(row * SROWH + c8) * 2u, src, 16);
        }
        asm volatile("cp.async.commit_group;" ::: "memory");
    };

    // per-lane ldmatrix address offsets (halves*2 = bytes)
    const uint32_t a_off = (uint32_t)(((wm * 64 + (lane & 15)) * SROWH + 8 * (lane >> 4)) * 2);
    const uint32_t b_off = (uint32_t)((((lane & 7) + ((lane & 16) >> 1)) * SROWH
                                       + ((lane & 8) ? 8 : 0)) * 2);

    load_stage(0, 0);
    load_stage(1, BK);

    int st = 0;
    for (int kt = 0; kt < NKT; kt++) {
        if (kt + 1 < NKT) asm volatile("cp.async.wait_group 1;" ::: "memory");
        else              asm volatile("cp.async.wait_group 0;" ::: "memory");
        __syncthreads();
        if (kt + 2 < NKT) load_stage((kt + 2) % 3, (kt + 2) * BK);

        const uint32_t ab = smb + (uint32_t)(st * STAGE_BYTES);
        const uint32_t bb = ab + A_BYTES;
#pragma unroll
        for (int k16 = 0; k16 < 4; k16++) {
            const int kk = k16 * 16;
            uint32_t af[4][4], bf[4][2];
#pragma unroll
            for (int mt = 0; mt < 4; mt++)
                ldm_x4(af[mt][0], af[mt][1], af[mt][2], af[mt][3],
                       ab + a_off + (uint32_t)((mt * 16 * SROWH + kk) * 2));
#pragma unroll
            for (int p = 0; p < 2; p++)
                ldm_x4(bf[2 * p][0], bf[2 * p][1], bf[2 * p + 1][0], bf[2 * p + 1][1],
                       bb + b_off + (uint32_t)(((wn * 32 + p * 16) * SROWH + kk) * 2));
#pragma unroll
            for (int mt = 0; mt < 4; mt++)
#pragma unroll
                for (int nt = 0; nt < 4; nt++)
                    mma_bf16(acc[mt][nt][0], acc[mt][nt][1], acc[mt][nt][2], acc[mt][nt][3],
                             af[mt][0], af[mt][1], af[mt][2], af[mt][3],
                             bf[nt][0], bf[nt][1]);
        }
        st = (st + 1) % 3;
    }

    // epilogue
#pragma unroll
    for (int mt = 0; mt < 4; mt++) {
        const int ra = m0 + wm * 64 + mt * 16 + tg;
        const int rb = ra + 8;
#pragma unroll
        for (int nt = 0; nt < 4; nt++) {
            const int colg = n0 + wn * 32 + nt * 8 + t4 * 2;
            const int half = colg >> 10;
            const int col  = colg & 1023;
            const float* bias = half ? bias1 : bias0;
            float* C = half ? C1 : C0;
            const int act = half ? act1 : act0;
            const float bx = bias[col], by = bias[col + 1];
            float v0 = acc[mt][nt][0] + bx;
            float v1 = acc[mt][nt][1] + by;
            float v2 = acc[mt][nt][2] + bx;
            float v3 = acc[mt][nt][3] + by;
            if (act) { v0 = gelu_f(v0); v1 = gelu_f(v1); v2 = gelu_f(v2); v3 = gelu_f(v3); }
            if (ra < M) *(float2*)(C + (size_t)ra * 1024 + col) = make_float2(v0, v1);
            if (rb < M) *(float2*)(C + (size_t)rb * 1024 + col) = make_float2(v2, v3);
        }
    }
}

// ---------------- k/v projection (masked), head-friendly layouts ------------
__global__ void __launch_bounds__(128)
kv_k(const float* __restrict__ l, const float* __restrict__ lm,
     const float* __restrict__ fkw, const float* __restrict__ fkb,
     const float* __restrict__ fvw, const float* __restrict__ fvb,
     float* __restrict__ kg, float* __restrict__ vg)
{
    extern __shared__ float l_sm[];
    __shared__ float mask_sm[NL];
    const int h = blockIdx.x, b = blockIdx.y;
    const int tid = threadIdx.x;

    for (int idx = tid; idx < NL * LIN; idx += 128)
        l_sm[idx] = l[(size_t)b * NL * LIN + idx];
    if (tid < NL) mask_sm[tid] = lm[b * NL + tid];
    __syncthreads();

    const int c = h * DK + tid;
    const float* wk = fkw + (size_t)c * LIN;
    const float* wv = fvw + (size_t)c * LIN;

    float ak[NL], av[NL];
#pragma unroll
    for (int n = 0; n < NL; n++) { ak[n] = 0.f; av[n] = 0.f; }
    for (int i = 0; i < LIN; i++) {
        const float a = wk[i];
        const float v = wv[i];
#pragma unroll
        for (int n = 0; n < NL; n++) {
            const float lv = l_sm[n * LIN + i];
            ak[n] = fmaf(a, lv, ak[n]);
            av[n] = fmaf(v, lv, av[n]);
        }
    }
    const float kb = fkb[c], vb = fvb[c];
    const size_t base = (size_t)(b * NH + h) * (DK * NL);
#pragma unroll
    for (int n = 0; n < NL; n++) {
        const float mk = mask_sm[n];
        kg[base + tid * NL + n] = (ak[n] + kb) * mk;
        vg[base + n * DK + tid] = (av[n] + vb) * mk;
    }
}

// ---------------- instance-norm stats ---------------------------------------
__global__ void __launch_bounds__(256)
stats_k(const float* __restrict__ C, float2* __restrict__ st)
{
    __shared__ float s1[4][64];
    __shared__ float s2[4][64];
    const int b  = blockIdx.y;
    const int cg = blockIdx.x * 64;
    const int tc = threadIdx.x & 63;
    const int tr = threadIdx.x >> 6;
    const float* base = C + (size_t)b * HW * 1024 + cg + tc;
    float a = 0.f, a2 = 0.f;
    for (int r = tr; r < HW; r += 4) {
        const float v = base[(size_t)r * 1024];
        a += v; a2 += v * v;
    }
    s1[tr][tc] = a; s2[tr][tc] = a2;
    __syncthreads();
    if (tr == 0) {
        a  = s1[0][tc] + s1[1][tc] + s1[2][tc] + s1[3][tc];
        a2 = s2[0][tc] + s2[1][tc] + s2[2][tc] + s2[3][tc];
        const float inv = 1.0f / (float)HW;
        const float mean = a * inv;
        const float var  = a2 * inv - mean * mean;
        st[b * 1024 + cg + tc] = make_float2(mean, rsqrtf(var + 1e-5f));
    }
}

// ---------------- attention (writes split-bf16 acat directly) ---------------
__global__ void __launch_bounds__(128)
attn_k(const float* __restrict__ q, const float* __restrict__ kg,
       const float* __restrict__ vg, const float2* __restrict__ sq,
       const float* __restrict__ lm, __nv_bfloat16* __restrict__ acat)
{
    extern __shared__ float smn[];
    float* q_sm = smn;
    float* k_sm = smn + 8192;
    float* v_sm = smn + 12288;
    float* p_sm = smn + 16384;
    float* b_sm = smn + 18432;

    const int b = blockIdx.z, h = blockIdx.y;
    const int r0 = blockIdx.x * 64;
    const int tid = threadIdx.x;
    const int lane = tid & 31, wi = tid >> 5;

    const size_t headoff = (size_t)(b * NH + h) * (DK * NL);
    for (int idx = tid; idx < DK * NL; idx += 128) {
        k_sm[idx] = kg[headoff + idx];
        v_sm[idx] = vg[headoff + idx];
    }
    if (tid < NL) b_sm[tid] = 10000.0f * (lm[b * NL + tid] - 1.0f);

    const float2 st = sq[b * 1024 + h * DK + tid];
    const size_t qbase = (size_t)b * HW * 1024 + h * DK + tid;
#pragma unroll 4
    for (int r = 0; r < 64; r++) {
        const int row = r0 + r;
        const float val = (row < HW) ? q[qbase + (size_t)row * 1024] : 0.f;
        q_sm[r * 128 + tid] = (val - st.x) * st.y;
    }
    __syncthreads();

    for (int rp = 0; rp < 16; rp += 2) {
        const int ra = wi * 16 + rp;
        const float* qa = q_sm + ra * 128;
        const float* qb = qa + 128;
        float s0 = 0.f, s1 = 0.f;
#pragma unroll 8
        for (int d = 0; d < 128; d++) {
            const float kk = k_sm[d * 32 + lane];
            s0 = fmaf(qa[d], kk, s0);
            s1 = fmaf(qb[d], kk, s1);
        }
        s0 = s0 * 0.03125f + b_sm[lane];
        s1 = s1 * 0.03125f + b_sm[lane];
        float m0 = s0, m1 = s1;
#pragma unroll
        for (int off = 16; off; off >>= 1) {
            m0 = fmaxf(m0, __shfl_xor_sync(0xffffffffu, m0, off));
            m1 = fmaxf(m1, __shfl_xor_sync(0xffffffffu, m1, off));
        }
        const float e0 = __expf(s0 - m0);
        const float e1 = __expf(s1 - m1);
        float t0 = e0, t1 = e1;
#pragma unroll
        for (int off = 16; off; off >>= 1) {
            t0 += __shfl_xor_sync(0xffffffffu, t0, off);
            t1 += __shfl_xor_sync(0xffffffffu, t1, off);
        }
        p_sm[ra * 32 + lane]       = e0 / t0;
        p_sm[(ra + 1) * 32 + lane] = e1 / t1;
    }
    __syncthreads();

    const int c = h * DK + tid;
    for (int r = 0; r < 64; r += 4) {
        float ov[4] = {0.f, 0.f, 0.f, 0.f};
#pragma unroll
        for (int n = 0; n < NL; n++) {
            const float vv = v_sm[n * 128 + tid];
            ov[0] = fmaf(p_sm[(r + 0) * 32 + n], vv, ov[0]);
            ov[1] = fmaf(p_sm[(r + 1) * 32 + n], vv, ov[1]);
            ov[2] = fmaf(p_sm[(r + 2) * 32 + n], vv, ov[2]);
            ov[3] = fmaf(p_sm[(r + 3) * 32 + n], vv, ov[3]);
        }
#pragma unroll
        for (int j = 0; j < 4; j++) {
            const int row = r0 + r + j;
            if (row >= HW) break;
            const float v = ov[j];
            const __nv_bfloat16 hi = __float2bfloat16_rn(v);
            const __nv_bfloat16 lo = __float2bfloat16_rn(v - __bfloat162float(hi));
            const size_t abase = ((size_t)b * HW + row) * KCAT + c;
            acat[abase]        = hi;
            acat[abase + 1024] = lo;
            acat[abase + 2048] = hi;
        }
    }
}

// ---------------- gated fusion: acat = split(vis * inorm(lang)) -------------
__global__ void __launch_bounds__(256)
mm_k(const float* __restrict__ vis, const float* __restrict__ lang,
     const float2* __restrict__ sl, __nv_bfloat16* __restrict__ acat)
{
    const int i4 = blockIdx.x * blockDim.x + threadIdx.x;
    const int total4 = (RTOT * 1024) / 4;
    if (i4 >= total4) return;
    const size_t idx = (size_t)i4 * 4;
    const size_t r = idx >> 10;
    const int b = (int)(r / HW);
    const int c = (int)(idx & 1023);
    const float2 s0 = sl[b * 1024 + c + 0];
    const float2 s1 = sl[b * 1024 + c + 1];
    const float2 s2 = sl[b * 1024 + c + 2];
    const float2 s3 = sl[b * 1024 + c + 3];
    const float4 vv = *(const float4*)(vis + idx);
    const float4 lv = *(const float4*)(lang + idx);
    float o0 = vv.x * ((lv.x - s0.x) * s0.y);
    float o1 = vv.y * ((lv.y - s1.x) * s1.y);
    float o2 = vv.z * ((lv.z - s2.x) * s2.y);
    float o3 = vv.w * ((lv.w - s3.x) * s3.y);
    __nv_bfloat16 h0 = __float2bfloat16_rn(o0);
    __nv_bfloat16 h1 = __float2bfloat16_rn(o1);
    __nv_bfloat16 h2 = __float2bfloat16_rn(o2);
    __nv_bfloat16 h3 = __float2bfloat16_rn(o3);
    __nv_bfloat16 l0 = __float2bfloat16_rn(o0 - __bfloat162float(h0));
    __nv_bfloat16 l1 = __float2bfloat16_rn(o1 - __bfloat162float(h1));
    __nv_bfloat16 l2 = __float2bfloat16_rn(o2 - __bfloat162float(h2));
    __nv_bfloat16 l3 = __float2bfloat16_rn(o3 - __bfloat162float(h3));
    __nv_bfloat16* base = acat + r * KCAT + c;
    ushort4 hv = make_ushort4(*(unsigned short*)&h0, *(unsigned short*)&h1,
                              *(unsigned short*)&h2, *(unsigned short*)&h3);
    ushort4 lv4 = make_ushort4(*(unsigned short*)&l0, *(unsigned short*)&l1,
                               *(unsigned short*)&l2, *(unsigned short*)&l3);
    *(ushort4*)(base)        = hv;
    *(ushort4*)(base + 1024) = lv4;
    *(ushort4*)(base + 2048) = hv;
}

// ---------------- launcher ---------------------------------------------------
extern "C" void kernel_launch(void* const* d_in, const int* in_sizes, int n_in,
                              void* d_out, int out_size)
{
    const float* x      = (const float*)d_in[0];
    const float* l      = (const float*)d_in[1];
    const float* l_mask = (const float*)d_in[2];
    const float* vis_w  = (const float*)d_in[3];
    const float* vis_b  = (const float*)d_in[4];
    const float* fq_w   = (const float*)d_in[5];
    const float* fq_b   = (const float*)d_in[6];
    const float* fk_w   = (const float*)d_in[7];
    const float* fk_b   = (const float*)d_in[8];
    const float* fv_w   = (const float*)d_in[9];
    const float* fv_b   = (const float*)d_in[10];
    const float* W_w    = (const float*)d_in[11];
    const float* W_b    = (const float*)d_in[12];
    const float* pm_w   = (const float*)d_in[13];
    const float* pm_b   = (const float*)d_in[14];
    float* out = (float*)d_out;

    float *pvis, *pq, *plang, *pk, *pv;
    __nv_bfloat16 *pacat, *pwcat;
    float2 *psq, *psl;
    cudaGetSymbolAddress((void**)&pvis,  g_vis);
    cudaGetSymbolAddress((void**)&pq,    g_q);
    cudaGetSymbolAddress((void**)&plang, g_lang);
    cudaGetSymbolAddress((void**)&pacat, g_acat);
    cudaGetSymbolAddress((void**)&pwcat, g_wcat);
    cudaGetSymbolAddress((void**)&pk,    g_k);
    cudaGetSymbolAddress((void**)&pv,    g_v);
    cudaGetSymbolAddress((void**)&psq,   g_sq);
    cudaGetSymbolAddress((void**)&psl,   g_sl);
    __nv_bfloat16* wc01 = pwcat;                              // vis rows 0-1023, fq rows 1024-2047
    __nv_bfloat16* wc1  = pwcat + (size_t)1024 * KCAT;
    __nv_bfloat16* wc2  = pwcat + (size_t)2 * 1024 * KCAT;
    __nv_bfloat16* wc3  = pwcat + (size_t)3 * 1024 * KCAT;

    cudaFuncSetAttribute(kv_k,    cudaFuncAttributeMaxDynamicSharedMemorySize, NL * LIN * 4);
    cudaFuncSetAttribute(attn_k,  cudaFuncAttributeMaxDynamicSharedMemorySize, 18464 * 4);
    cudaFuncSetAttribute(tgemm_k, cudaFuncAttributeMaxDynamicSharedMemorySize, GEMM_SMEM);

    const int MT = (RTOT + BM - 1) / BM;

    // weight splits: [hi | hi | lo]
    conv_k<<<1024, 256>>>(vis_w, wc01, 1024, 2048, 1024);
    conv_k<<<1024, 256>>>(fq_w,  wc1,  1024, 2048, 1024);
    conv_k<<<1024, 256>>>(W_w,   wc2,  1024, 2048, 1024);
    conv_k<<<1024, 256>>>(pm_w,  wc3,  1024, 2048, 1024);

    // k,v projection (masked)
    kv_k<<<dim3(NH, BB), 128, NL * LIN * 4>>>(l, l_mask, fk_w, fk_b, fv_w, fv_b, pk, pv);

    // x split: [hi | lo | hi]
    conv_k<<<RTOT, 256>>>(x, pacat, RTOT, 1024, 2048);

    // fused: vis = GELU(x@vis_w^T+b), q = x@fq_w^T+b   (N=2048, W rows stacked)
    tgemm_k<<<dim3(2048 / BN, MT), 512, GEMM_SMEM>>>(
        pacat, wc01, vis_b, fq_b, pvis, pq, RTOT, 1, 0);

    // q stats
    stats_k<<<dim3(16, BB), 256>>>(pq, psq);
    // attention -> split acat
    attn_k<<<dim3((HW + 63) / 64, NH, BB), 128, 18464 * 4>>>(pq, pk, pv, psq, l_mask, pacat);
    // lang = O @ W_w^T + b
    tgemm_k<<<dim3(1024 / BN, MT), 512, GEMM_SMEM>>>(
        pacat, wc2, W_b, W_b, plang, plang, RTOT, 0, 0);
    // lang stats
    stats_k<<<dim3(16, BB), 256>>>(plang, psl);
    // mm = vis * inorm(lang) -> split acat
    mm_k<<<(RTOT * 1024 / 4 + 255) / 256, 256>>>(pvis, plang, psl, pacat);
    // out = GELU(mm @ pm_w^T + b)
    tgemm_k<<<dim3(1024 / BN, MT), 512, GEMM_SMEM>>>(
        pacat, wc3, pm_b, pm_b, out, out, RTOT, 1, 1);
}